// round 4
// baseline (speedup 1.0000x reference)
#include <cuda_runtime.h>
#include <math.h>

#define N_NODES 100000
#define N_EDGES 3200000
#define IN_DIM 512
#define HIDDEN 16
#define N_CLASSES 7
#define NBLK 391          // ceil(100000/256)

// ---------------- scratch (device globals; no allocation) ----------------
__device__ int   g_deg[N_NODES];
__device__ int   g_rowptr[N_NODES + 1];
__device__ int   g_fill[N_NODES];
__device__ int   g_adj[N_EDGES];
__device__ float g_dinv[N_NODES];
__device__ int   g_bsum[NBLK];
__device__ float g_h1[N_NODES * HIDDEN];    // after k_scale: dinv[i] * (x@W1)[i]
__device__ float g_y2[N_NODES * N_CLASSES]; // dinv[i] * (relu(...)@W2)[i]

// ---------------- CSR build ----------------
__global__ void k_zero_deg() {
    int i = blockIdx.x * blockDim.x + threadIdx.x;
    if (i < N_NODES) g_deg[i] = 0;
}

// 4 edges per thread (int4)
__global__ void k_count(const int4* __restrict__ dst4) {
    int e = blockIdx.x * blockDim.x + threadIdx.x;
    if (e < N_EDGES / 4) {
        int4 d = dst4[e];
        atomicAdd(&g_deg[d.x], 1);
        atomicAdd(&g_deg[d.y], 1);
        atomicAdd(&g_deg[d.z], 1);
        atomicAdd(&g_deg[d.w], 1);
    }
}

// pass 1: per-block sums of deg
__global__ void k_s1() {
    int t = threadIdx.x;
    int i = blockIdx.x * 256 + t;
    int lane = t & 31, w = t >> 5;
    int v = (i < N_NODES) ? g_deg[i] : 0;
    #pragma unroll
    for (int o = 16; o > 0; o >>= 1) v += __shfl_down_sync(0xffffffffu, v, o);
    __shared__ int ws[8];
    if (lane == 0) ws[w] = v;
    __syncthreads();
    if (t == 0) {
        int s = 0;
        #pragma unroll
        for (int k = 0; k < 8; k++) s += ws[k];
        g_bsum[blockIdx.x] = s;
    }
}

// pass 2 (merged s2+s3): each block reduces preceding block sums for its
// offset, then block-local exclusive scan -> rowptr/fill; fused dinv prep.
__global__ void k_s3() {
    int t = threadIdx.x;           // 256 threads
    int b = blockIdx.x;
    int lane = t & 31, w = t >> 5;
    __shared__ int ws[8], wsp[8];
    __shared__ int s_off;

    // block offset = sum_{k<b} g_bsum[k]  (block reduce over <=391 values)
    int partial = 0;
    for (int k = t; k < b; k += 256) partial += g_bsum[k];
    #pragma unroll
    for (int o = 16; o > 0; o >>= 1) partial += __shfl_down_sync(0xffffffffu, partial, o);
    if (lane == 0) ws[w] = partial;
    __syncthreads();
    if (t == 0) {
        int s = 0;
        #pragma unroll
        for (int k = 0; k < 8; k++) s += ws[k];
        s_off = s;
        if (b == NBLK - 1) g_rowptr[N_NODES] = s + g_bsum[NBLK - 1];
    }
    __syncthreads();

    // block-local exclusive scan of deg
    int i = b * 256 + t;
    int v = (i < N_NODES) ? g_deg[i] : 0;
    int x = v;
    #pragma unroll
    for (int o = 1; o < 32; o <<= 1) {
        int u = __shfl_up_sync(0xffffffffu, x, o);
        if (lane >= o) x += u;
    }
    if (lane == 31) ws[w] = x;
    __syncthreads();
    if (t < 8) {
        int s = ws[t];
        #pragma unroll
        for (int o = 1; o < 8; o <<= 1) {
            int u = __shfl_up_sync(0x000000ffu, s, o);
            if (t >= o) s += u;
        }
        wsp[t] = s;
    }
    __syncthreads();
    int excl = x - v + (w > 0 ? wsp[w - 1] : 0) + s_off;
    if (i < N_NODES) {
        g_rowptr[i] = excl;
        g_fill[i] = excl;
        g_dinv[i] = rsqrtf((float)(v + 1));  // +1 self loop
    }
}

// 4 edges per thread (int4)
__global__ void k_fill(const int4* __restrict__ src4,
                       const int4* __restrict__ dst4) {
    int e = blockIdx.x * blockDim.x + threadIdx.x;
    if (e < N_EDGES / 4) {
        int4 s = src4[e];
        int4 d = dst4[e];
        g_adj[atomicAdd(&g_fill[d.x], 1)] = s.x;
        g_adj[atomicAdd(&g_fill[d.y], 1)] = s.y;
        g_adj[atomicAdd(&g_fill[d.z], 1)] = s.z;
        g_adj[atomicAdd(&g_fill[d.w], 1)] = s.w;
    }
}

// ---------------- GEMM1: g_h1 = x @ W1 (raw; dinv applied by k_scale) ------
// BM=256 rows/block, BN=16 (all cols), BK=16. 256 threads, each TM=4 x TN=4.
#define BM 256
#define BK 16
#define XS_PAD 4

__global__ __launch_bounds__(256) void k_gemm1(const float* __restrict__ x,
                                               const float* __restrict__ W1) {
    __shared__ float xs[BK][BM + XS_PAD];   // transposed: xs[k][row]
    __shared__ float ws[BK][HIDDEN];
    int tid = threadIdx.x;
    int rg = tid & 63;       // row group: rows rg*4 .. rg*4+3
    int cg = tid >> 6;       // col group: cols cg*4 .. cg*4+3
    int row0 = blockIdx.x * BM;

    float acc[4][4] = {};

    for (int k0 = 0; k0 < IN_DIM; k0 += BK) {
        #pragma unroll
        for (int it = 0; it < 4; it++) {
            int f = tid + it * 256;      // 0..1023 float4 slots
            int r = f >> 2;
            int kk = (f & 3) << 2;
            int grow = row0 + r;
            float4 v = make_float4(0.f, 0.f, 0.f, 0.f);
            if (grow < N_NODES)
                v = *(const float4*)&x[(size_t)grow * IN_DIM + k0 + kk];
            xs[kk + 0][r] = v.x;
            xs[kk + 1][r] = v.y;
            xs[kk + 2][r] = v.z;
            xs[kk + 3][r] = v.w;
        }
        {
            int k = tid >> 4, j = tid & 15;
            ws[k][j] = W1[(k0 + k) * HIDDEN + j];
        }
        __syncthreads();
        #pragma unroll
        for (int k = 0; k < BK; k++) {
            float4 xv = *(const float4*)&xs[k][rg * 4];
            float4 wv = *(const float4*)&ws[k][cg * 4];
            acc[0][0] += xv.x * wv.x; acc[0][1] += xv.x * wv.y; acc[0][2] += xv.x * wv.z; acc[0][3] += xv.x * wv.w;
            acc[1][0] += xv.y * wv.x; acc[1][1] += xv.y * wv.y; acc[1][2] += xv.y * wv.z; acc[1][3] += xv.y * wv.w;
            acc[2][0] += xv.z * wv.x; acc[2][1] += xv.z * wv.y; acc[2][2] += xv.z * wv.z; acc[2][3] += xv.z * wv.w;
            acc[3][0] += xv.w * wv.x; acc[3][1] += xv.w * wv.y; acc[3][2] += xv.w * wv.z; acc[3][3] += xv.w * wv.w;
        }
        __syncthreads();
    }

    #pragma unroll
    for (int i = 0; i < 4; i++) {
        int r = row0 + rg * 4 + i;
        if (r < N_NODES) {
            float4 o = make_float4(acc[i][0], acc[i][1], acc[i][2], acc[i][3]);
            *(float4*)&g_h1[r * HIDDEN + cg * 4] = o;
        }
    }
}

// apply dinv to h1 (float4 over N_NODES*HIDDEN)
__global__ void k_scale() {
    int f = blockIdx.x * blockDim.x + threadIdx.x;
    if (f < N_NODES * HIDDEN / 4) {
        int node = f >> 2;
        float dv = g_dinv[node];
        float4 v = ((float4*)g_h1)[f];
        v.x *= dv; v.y *= dv; v.z *= dv; v.w *= dv;
        ((float4*)g_h1)[f] = v;
    }
}

// ---------------- Layer-1 aggregation + relu + W2 GEMM fused ----------------
__global__ __launch_bounds__(256) void k_agg1(const float* __restrict__ b1,
                                              const float* __restrict__ W2) {
    __shared__ float sW2[HIDDEN * N_CLASSES];
    __shared__ float sb1[HIDDEN];
    int tid = threadIdx.x;
    if (tid < HIDDEN * N_CLASSES) sW2[tid] = W2[tid];
    if (tid < HIDDEN) sb1[tid] = b1[tid];
    __syncthreads();

    int lane = tid & 31;
    int wid = tid >> 5;
    int half = lane >> 4;
    int j = lane & 15;
    int node = (blockIdx.x * 8 + wid) * 2 + half;
    if (node >= N_NODES) return;
    unsigned mask = 0xFFFFu << (half * 16);
    int base = half * 16;

    float acc = g_h1[node * HIDDEN + j];   // self-loop term
    int pos = g_rowptr[node];
    int end = g_rowptr[node + 1];
    while (pos < end) {
        int cnt = end - pos;
        if (cnt > 16) cnt = 16;
        int src = (j < cnt) ? g_adj[pos + j] : 0;
        int i = 0;
        for (; i + 8 <= cnt; i += 8) {
            int s0 = __shfl_sync(mask, src, base + i);
            int s1 = __shfl_sync(mask, src, base + i + 1);
            int s2 = __shfl_sync(mask, src, base + i + 2);
            int s3 = __shfl_sync(mask, src, base + i + 3);
            int s4 = __shfl_sync(mask, src, base + i + 4);
            int s5 = __shfl_sync(mask, src, base + i + 5);
            int s6 = __shfl_sync(mask, src, base + i + 6);
            int s7 = __shfl_sync(mask, src, base + i + 7);
            float v0 = g_h1[s0 * HIDDEN + j];
            float v1 = g_h1[s1 * HIDDEN + j];
            float v2 = g_h1[s2 * HIDDEN + j];
            float v3 = g_h1[s3 * HIDDEN + j];
            float v4 = g_h1[s4 * HIDDEN + j];
            float v5 = g_h1[s5 * HIDDEN + j];
            float v6 = g_h1[s6 * HIDDEN + j];
            float v7 = g_h1[s7 * HIDDEN + j];
            acc += ((v0 + v1) + (v2 + v3)) + ((v4 + v5) + (v6 + v7));
        }
        for (; i < cnt; i++) {
            int s = __shfl_sync(mask, src, base + i);
            acc += g_h1[s * HIDDEN + j];
        }
        pos += cnt;
    }

    float dv = g_dinv[node];
    float y = fmaxf(dv * acc + sb1[j], 0.f);  // relu(agg + b1)

    #pragma unroll
    for (int c = 0; c < N_CLASSES; c++) {
        float t = y * sW2[j * N_CLASSES + c];
        t += __shfl_xor_sync(mask, t, 1);
        t += __shfl_xor_sync(mask, t, 2);
        t += __shfl_xor_sync(mask, t, 4);
        t += __shfl_xor_sync(mask, t, 8);
        if (j == c) g_y2[node * N_CLASSES + c] = dv * t;
    }
}

// ---------------- Layer-2 aggregation + bias + log_softmax ----------------
__global__ __launch_bounds__(256) void k_agg2(const float* __restrict__ b2,
                                              float* __restrict__ out) {
    int tid = threadIdx.x;
    int lane = tid & 31;
    int wid = tid >> 5;
    int sub = lane >> 3;            // 0..3
    int j = lane & 7;               // 0..7 (lane 7 inactive for data)
    int node = (blockIdx.x * 8 + wid) * 4 + sub;
    if (node >= N_NODES) return;
    unsigned mask = 0xFFu << (sub * 8);
    int base = sub * 8;
    int jr = (j < N_CLASSES) ? j : 0;

    float acc = (j < N_CLASSES) ? g_y2[node * N_CLASSES + j] : 0.f;
    int pos = g_rowptr[node];
    int end = g_rowptr[node + 1];
    while (pos < end) {
        int cnt = end - pos;
        if (cnt > 8) cnt = 8;
        int src = (j < cnt) ? g_adj[pos + j] : 0;
        int i = 0;
        for (; i + 4 <= cnt; i += 4) {
            int s0 = __shfl_sync(mask, src, base + i);
            int s1 = __shfl_sync(mask, src, base + i + 1);
            int s2 = __shfl_sync(mask, src, base + i + 2);
            int s3 = __shfl_sync(mask, src, base + i + 3);
            float v0 = g_y2[s0 * N_CLASSES + jr];
            float v1 = g_y2[s1 * N_CLASSES + jr];
            float v2 = g_y2[s2 * N_CLASSES + jr];
            float v3 = g_y2[s3 * N_CLASSES + jr];
            acc += (v0 + v1) + (v2 + v3);
        }
        for (; i < cnt; i++) {
            int s = __shfl_sync(mask, src, base + i);
            acc += g_y2[s * N_CLASSES + jr];
        }
        pos += cnt;
    }

    float dv = g_dinv[node];
    float o = dv * acc + ((j < N_CLASSES) ? __ldg(&b2[jr]) : 0.f);

    float m = (j < N_CLASSES) ? o : -1e30f;
    m = fmaxf(m, __shfl_xor_sync(mask, m, 1));
    m = fmaxf(m, __shfl_xor_sync(mask, m, 2));
    m = fmaxf(m, __shfl_xor_sync(mask, m, 4));
    float e = (j < N_CLASSES) ? expf(o - m) : 0.f;
    float s = e;
    s += __shfl_xor_sync(mask, s, 1);
    s += __shfl_xor_sync(mask, s, 2);
    s += __shfl_xor_sync(mask, s, 4);
    float ls = logf(s);
    if (j < N_CLASSES) out[node * N_CLASSES + j] = o - m - ls;
}

// ---------------- launch ----------------
extern "C" void kernel_launch(void* const* d_in, const int* in_sizes, int n_in,
                              void* d_out, int out_size) {
    const float* x  = (const float*)d_in[0];
    const int*   ei = (const int*)d_in[1];
    const float* W1 = (const float*)d_in[2];
    const float* b1 = (const float*)d_in[3];
    const float* W2 = (const float*)d_in[4];
    const float* b2 = (const float*)d_in[5];
    float* out = (float*)d_out;

    const int4* src4 = (const int4*)ei;
    const int4* dst4 = (const int4*)(ei + N_EDGES);

    const int TB = 256;
    int gridN = (N_NODES + TB - 1) / TB;          // 391
    int gridE4 = (N_EDGES / 4 + TB - 1) / TB;     // 3125
    int gridG = (N_NODES + BM - 1) / BM;          // 391
    int gridS = (N_NODES * HIDDEN / 4 + TB - 1) / TB;

    k_zero_deg<<<gridN, TB>>>();                  // 0
    k_count<<<gridE4, TB>>>(dst4);                // 1
    k_s1<<<NBLK, 256>>>();                        // 2
    k_gemm1<<<gridG, 256>>>(x, W1);               // 3 <- profiled slot
    k_s3<<<NBLK, 256>>>();                        // 4
    k_fill<<<gridE4, TB>>>(src4, dst4);           // 5
    k_scale<<<gridS, TB>>>();                     // 6

    int grid1 = (N_NODES + 16 - 1) / 16;
    k_agg1<<<grid1, 256>>>(b1, W2);               // 7

    int grid2 = (N_NODES + 32 - 1) / 32;
    k_agg2<<<grid2, 256>>>(b2, out);              // 8
}